// round 1
// baseline (speedup 1.0000x reference)
#include <cuda_runtime.h>
#include <math.h>

// Problem constants (fixed shapes for this problem)
#define NMAX 40000
#define EMAX 640000
#define DD   128
#define HH   8
#define DKK  16
#define TT   3
#define RR   4
#define NB   8

// ---------------- scratch (device globals; no allocation allowed) -------------
__device__ float g_q   [NMAX * DD];           // Q projection per node
__device__ float g_sp  [NMAX * DD];           // speaker projection per node (x @ Vw[1] @ s2u)
__device__ float g_kt  [NMAX * RR * DD];      // k_t per (node, relation)
__device__ float g_vt  [NMAX * RR * DD];      // v_t per (node, relation)
__device__ float g_aggr[NMAX * DD];           // normalized aggregation per node
__device__ float g_Wsp [DD * DD];             // Vw[1] @ s2u
__device__ float g_bsp [DD];                  // Vb[1] @ s2u
__device__ int   g_win [NMAX];                // winning (max-index) type-0 edge per src node
__device__ int   g_thist[NMAX];               // histogram of edges per target
__device__ int   g_toff [NMAX + 1];           // CSR offsets by target
__device__ int   g_tcur [NMAX];               // scatter cursors
__device__ int   g_ebyt [EMAX];               // edge ids sorted by target
__device__ int   g_typehist[TT];
__device__ int   g_typecur [TT];
__device__ int   g_perm [NMAX];               // node ids sorted by node type

// ------------------------------- init / histograms ---------------------------
__global__ void k_zero(int n) {
    int i = blockIdx.x * blockDim.x + threadIdx.x;
    if (i < n) { g_win[i] = -1; g_thist[i] = 0; }
    if (i < TT) g_typehist[i] = 0;
}

__global__ void k_nodehist(const int* __restrict__ ntype, int n) {
    int i = blockIdx.x * blockDim.x + threadIdx.x;
    if (i < n) atomicAdd(&g_typehist[ntype[i]], 1);
}

__global__ void k_edgestats(const int* __restrict__ ei, const int* __restrict__ et, int e) {
    int i = blockIdx.x * blockDim.x + threadIdx.x;
    if (i >= e) return;
    int tgt = ei[e + i];
    atomicAdd(&g_thist[tgt], 1);
    if (et[i] == 0) atomicMax(&g_win[ei[i]], i);   // last (max-index) edge wins
}

// single-block chunked scan of g_thist -> g_toff / g_tcur; also type offsets
__global__ void k_scan(int n) {
    __shared__ int buf[1024];
    __shared__ int carry_s;
    int t = threadIdx.x;
    if (t == 0) carry_s = 0;
    __syncthreads();
    for (int base = 0; base < n; base += 1024) {
        int v = (base + t < n) ? g_thist[base + t] : 0;
        buf[t] = v;
        __syncthreads();
        for (int off = 1; off < 1024; off <<= 1) {
            int x = (t >= off) ? buf[t - off] : 0;
            __syncthreads();
            buf[t] += x;
            __syncthreads();
        }
        int incl = buf[t];
        int excl = incl - v + carry_s;
        if (base + t < n) { g_toff[base + t] = excl; g_tcur[base + t] = excl; }
        __syncthreads();
        if (t == 1023) carry_s += incl;
        __syncthreads();
    }
    if (t == 0) {
        g_toff[n] = carry_s;
        int o = 0;
        for (int ty = 0; ty < TT; ty++) { g_typecur[ty] = o; o += g_typehist[ty]; }
    }
}

__global__ void k_scatter_edges(const int* __restrict__ ei, int e) {
    int i = blockIdx.x * blockDim.x + threadIdx.x;
    if (i >= e) return;
    int tgt = ei[e + i];
    int pos = atomicAdd(&g_tcur[tgt], 1);
    g_ebyt[pos] = i;
}

__global__ void k_scatter_nodes(const int* __restrict__ ntype, int n) {
    int i = blockIdx.x * blockDim.x + threadIdx.x;
    if (i >= n) return;
    int pos = atomicAdd(&g_typecur[ntype[i]], 1);
    g_perm[pos] = i;
}

// ------------------------- Wsp = Vw[1] @ s2u ; bsp = Vb[1] @ s2u --------------
__global__ void k_wsp(const float* __restrict__ Vw, const float* __restrict__ Vb,
                      const float* __restrict__ s2u) {
    int b = blockIdx.x;
    int d = threadIdx.x;
    float acc = 0.f;
    if (b < DD) {
        for (int m = 0; m < DD; m++)
            acc += Vw[(DD + b) * DD + m] * s2u[m * DD + d];
        g_Wsp[b * DD + d] = acc;
    } else {
        for (int m = 0; m < DD; m++)
            acc += Vb[DD + m] * s2u[m * DD + d];
        g_bsp[d] = acc;
    }
}

// ----- projections (K,Q,V,speaker) + per-relation head transforms, fused -----
__global__ void __launch_bounds__(128)
k_proj(const float* __restrict__ x, const int* __restrict__ ntype,
       const float* __restrict__ Kw, const float* __restrict__ Kb,
       const float* __restrict__ Qw, const float* __restrict__ Qb,
       const float* __restrict__ Vw, const float* __restrict__ Vb,
       const float* __restrict__ Ratt, const float* __restrict__ Rmsg, int n) {
    __shared__ float xs[NB][DD];
    __shared__ float ks[NB][DD];
    __shared__ float vs[NB][DD];
    __shared__ int nodes_s[NB], types_s[NB];
    int d = threadIdx.x;
    int base = blockIdx.x * NB;
    if (d < NB) {
        int idx = base + d;
        int nd = (idx < n) ? g_perm[idx] : -1;
        nodes_s[d] = nd;
        types_s[d] = (nd >= 0) ? ntype[nd] : 0;
    }
    __syncthreads();
    int nodes[NB], tj[NB];
#pragma unroll
    for (int j = 0; j < NB; j++) { nodes[j] = nodes_s[j]; tj[j] = types_s[j]; }
#pragma unroll
    for (int j = 0; j < NB; j++)
        xs[j][d] = (nodes[j] >= 0) ? x[nodes[j] * DD + d] : 0.f;
    __syncthreads();

    int tmin = tj[0], tmax = tj[0];
#pragma unroll
    for (int j = 1; j < NB; j++) { tmin = min(tmin, tj[j]); tmax = max(tmax, tj[j]); }

    float aK[NB], aQ[NB], aV[NB], aS[NB];
#pragma unroll
    for (int j = 0; j < NB; j++) {
        aK[j] = Kb[tj[j] * DD + d];
        aQ[j] = Qb[tj[j] * DD + d];
        aV[j] = Vb[tj[j] * DD + d];
        aS[j] = g_bsp[d];
    }

    if (tmin == tmax) {
        int t = tmin;
#pragma unroll 4
        for (int k = 0; k < DD; k++) {
            float ws = g_Wsp[k * DD + d];
            float wk = Kw[(t * DD + k) * DD + d];
            float wq = Qw[(t * DD + k) * DD + d];
            float wv = Vw[(t * DD + k) * DD + d];
            float xv[NB];
#pragma unroll
            for (int j = 0; j < NB; j++) xv[j] = xs[j][k];
#pragma unroll
            for (int j = 0; j < NB; j++) {
                aS[j] += xv[j] * ws;
                aK[j] += xv[j] * wk;
                aQ[j] += xv[j] * wq;
                aV[j] += xv[j] * wv;
            }
        }
    } else {
#pragma unroll 2
        for (int k = 0; k < DD; k++) {
            float ws = g_Wsp[k * DD + d];
            float xv[NB];
#pragma unroll
            for (int j = 0; j < NB; j++) xv[j] = xs[j][k];
#pragma unroll
            for (int j = 0; j < NB; j++) aS[j] += xv[j] * ws;
            for (int t = tmin; t <= tmax; t++) {
                float wk = Kw[(t * DD + k) * DD + d];
                float wq = Qw[(t * DD + k) * DD + d];
                float wv = Vw[(t * DD + k) * DD + d];
#pragma unroll
                for (int j = 0; j < NB; j++) {
                    if (tj[j] == t) {
                        aK[j] += xv[j] * wk;
                        aQ[j] += xv[j] * wq;
                        aV[j] += xv[j] * wv;
                    }
                }
            }
        }
    }

#pragma unroll
    for (int j = 0; j < NB; j++) {
        if (nodes[j] >= 0) {
            g_q [nodes[j] * DD + d] = aQ[j];
            g_sp[nodes[j] * DD + d] = aS[j];
        }
        ks[j][d] = aK[j];
        vs[j][d] = aV[j];
    }
    __syncthreads();

    // per-relation head transforms: kt = k @ Ratt[r][h], vt = v @ Rmsg[r][h]
    int h = d >> 4, f = d & 15;
    for (int r = 0; r < RR; r++) {
        float ar[DKK], am[DKK];
#pragma unroll
        for (int dk = 0; dk < DKK; dk++) {
            ar[dk] = Ratt[((r * HH + h) * DKK + dk) * DKK + f];
            am[dk] = Rmsg[((r * HH + h) * DKK + dk) * DKK + f];
        }
#pragma unroll
        for (int j = 0; j < NB; j++) {
            if (nodes[j] < 0) continue;
            float kt = 0.f, vt = 0.f;
#pragma unroll
            for (int dk = 0; dk < DKK; dk++) {
                kt += ks[j][(h << 4) + dk] * ar[dk];
                vt += vs[j][(h << 4) + dk] * am[dk];
            }
            g_kt[(nodes[j] * RR + r) * DD + d] = kt;
            g_vt[(nodes[j] * RR + r) * DD + d] = vt;
        }
    }
}

// ------------- attention: warp per target node, online softmax, no atomics ----
__global__ void k_attn(const int* __restrict__ ei, const int* __restrict__ et,
                       const int* __restrict__ ntype, const float* __restrict__ pri,
                       int n, int e) {
    int warp = (blockIdx.x * blockDim.x + threadIdx.x) >> 5;
    int lane = threadIdx.x & 31;
    if (warp >= n) return;
    int i  = warp;
    int d0 = lane * 4;
    int h  = lane >> 2;

    float4 q = *(const float4*)&g_q[i * DD + d0];
    int tt  = ntype[i];
    int beg = g_toff[i], end = g_toff[i + 1];

    float m = -INFINITY, den = 0.f;
    float4 acc = make_float4(0.f, 0.f, 0.f, 0.f);

    for (int idx = beg; idx < end; idx++) {
        int ed  = g_ebyt[idx];
        int src = ei[ed];
        int r   = et[ed];
        const float4 kt = *(const float4*)&g_kt[(src * RR + r) * DD + d0];
        float s = q.x * kt.x + q.y * kt.y + q.z * kt.z + q.w * kt.w;
        s += __shfl_xor_sync(0xffffffffu, s, 1);
        s += __shfl_xor_sync(0xffffffffu, s, 2);
        int st = ntype[src];
        float p   = pri[((tt * RR + r) * TT + st) * HH + h];
        float raw = s * p * 0.25f;
        float nm  = fmaxf(m, raw);
        float sc  = __expf(m - nm);
        float pe  = __expf(raw - nm);
        den = den * sc + pe;
        const float4 vt = *(const float4*)&g_vt[(src * RR + r) * DD + d0];
        acc.x = acc.x * sc + pe * vt.x;
        acc.y = acc.y * sc + pe * vt.y;
        acc.z = acc.z * sc + pe * vt.z;
        acc.w = acc.w * sc + pe * vt.w;
        m = nm;
    }
    float inv = 1.f / (den + 1e-16f);
    float4 o = make_float4(acc.x * inv, acc.y * inv, acc.z * inv, acc.w * inv);
    *(float4*)&g_aggr[i * DD + d0] = o;
}

// ------------- final: speaker add + GELU + per-type A projection + skip -------
__global__ void __launch_bounds__(128)
k_final(const float* __restrict__ x, const int* __restrict__ ntype,
        const int* __restrict__ ei,
        const float* __restrict__ Aw, const float* __restrict__ Ab,
        const float* __restrict__ skip, float* __restrict__ out, int n, int e) {
    __shared__ float gs[NB][DD];
    __shared__ int nodes_s[NB], types_s[NB];
    int d = threadIdx.x;
    int base = blockIdx.x * NB;
    if (d < NB) {
        int idx = base + d;
        int nd = (idx < n) ? g_perm[idx] : -1;
        nodes_s[d] = nd;
        types_s[d] = (nd >= 0) ? ntype[nd] : 0;
    }
    __syncthreads();
    int nodes[NB], tj[NB];
#pragma unroll
    for (int j = 0; j < NB; j++) { nodes[j] = nodes_s[j]; tj[j] = types_s[j]; }

#pragma unroll
    for (int j = 0; j < NB; j++) {
        float v = 0.f;
        if (nodes[j] >= 0) {
            v = g_aggr[nodes[j] * DD + d];
            int we = g_win[nodes[j]];
            if (we >= 0) {
                int tg = ei[e + we];
                v += g_sp[tg * DD + d];
            }
            v = 0.5f * v * (1.f + erff(v * 0.70710678118654752f));
        }
        gs[j][d] = v;
    }
    __syncthreads();

    int tmin = tj[0], tmax = tj[0];
#pragma unroll
    for (int j = 1; j < NB; j++) { tmin = min(tmin, tj[j]); tmax = max(tmax, tj[j]); }

    float aA[NB];
#pragma unroll
    for (int j = 0; j < NB; j++) aA[j] = Ab[tj[j] * DD + d];

    if (tmin == tmax) {
        int t = tmin;
#pragma unroll 4
        for (int k = 0; k < DD; k++) {
            float w = Aw[(t * DD + k) * DD + d];
            float xv[NB];
#pragma unroll
            for (int j = 0; j < NB; j++) xv[j] = gs[j][k];
#pragma unroll
            for (int j = 0; j < NB; j++) aA[j] += xv[j] * w;
        }
    } else {
#pragma unroll 2
        for (int k = 0; k < DD; k++) {
            float xv[NB];
#pragma unroll
            for (int j = 0; j < NB; j++) xv[j] = gs[j][k];
            for (int t = tmin; t <= tmax; t++) {
                float w = Aw[(t * DD + k) * DD + d];
#pragma unroll
                for (int j = 0; j < NB; j++)
                    if (tj[j] == t) aA[j] += xv[j] * w;
            }
        }
    }

#pragma unroll
    for (int j = 0; j < NB; j++) {
        if (nodes[j] < 0) continue;
        float sk = skip[tj[j]];
        float alpha = 1.f / (1.f + __expf(-sk));
        out[nodes[j] * DD + d] = aA[j] * alpha + x[nodes[j] * DD + d] * (1.f - alpha);
    }
}

// --------------------------------- launcher -----------------------------------
extern "C" void kernel_launch(void* const* d_in, const int* in_sizes, int n_in,
                              void* d_out, int out_size) {
    const float* node_inp  = (const float*)d_in[0];
    const int*   node_type = (const int*)  d_in[1];
    const int*   edge_index= (const int*)  d_in[2];
    const int*   edge_type = (const int*)  d_in[3];
    // d_in[4] node_position unused
    const float* Kw = (const float*)d_in[5];
    const float* Kb = (const float*)d_in[6];
    const float* Qw = (const float*)d_in[7];
    const float* Qb = (const float*)d_in[8];
    const float* Vw = (const float*)d_in[9];
    const float* Vb = (const float*)d_in[10];
    const float* Aw = (const float*)d_in[11];
    const float* Ab = (const float*)d_in[12];
    const float* pri  = (const float*)d_in[13];
    const float* Ratt = (const float*)d_in[14];
    const float* Rmsg = (const float*)d_in[15];
    const float* s2u  = (const float*)d_in[16];
    const float* skip = (const float*)d_in[17];
    float* out = (float*)d_out;

    int n = in_sizes[1];   // node_type count
    int e = in_sizes[3];   // edge_type count
    if (n > NMAX) n = NMAX;
    if (e > EMAX) e = EMAX;

    int nb = (n + 255) / 256;
    int eb = (e + 255) / 256;

    k_zero<<<nb, 256>>>(n);
    k_nodehist<<<nb, 256>>>(node_type, n);
    k_edgestats<<<eb, 256>>>(edge_index, edge_type, e);
    k_scan<<<1, 1024>>>(n);
    k_scatter_edges<<<eb, 256>>>(edge_index, e);
    k_scatter_nodes<<<nb, 256>>>(node_type, n);
    k_wsp<<<DD + 1, DD>>>(Vw, Vb, s2u);
    k_proj<<<(n + NB - 1) / NB, DD>>>(node_inp, node_type, Kw, Kb, Qw, Qb, Vw, Vb,
                                      Ratt, Rmsg, n);
    k_attn<<<(n + 7) / 8, 256>>>(edge_index, edge_type, node_type, pri, n, e);
    k_final<<<(n + NB - 1) / NB, DD>>>(node_inp, node_type, edge_index, Aw, Ab,
                                       skip, out, n, e);
}